// round 1
// baseline (speedup 1.0000x reference)
#include <cuda_runtime.h>
#include <cuda_bf16.h>
#include <math.h>

#define BB 4
#define CC 256
#define HH 200
#define WW 176
#define NN 128
#define GG 7
#define GP (GG * GG)   /* 49 */
#define CH 16          /* channels per chunk */
#define TS 405         /* padded per-channel tile stride (odd, coprime with 32) */
#define THREADS 256

__global__ __launch_bounds__(THREADS) void rotpool_kernel(
    const float* __restrict__ feat, const float* __restrict__ rois,
    const float* __restrict__ voxel, const int* __restrict__ stridep,
    float* __restrict__ out)
{
    __shared__ float tile[CH * TS];
    __shared__ float sout[CH * GP];
    __shared__ float six[GP], siy[GP];
    __shared__ int   ploc[GP], psx[GP], psy[GP];
    __shared__ float pw0[GP], pw1[GP], pw2[GP], pw3[GP];
    __shared__ int sxmin, sxmax, symin, symax;
    __shared__ int bxmin, bymin, bw, bh, sfits;

    const int tid = threadIdx.x;
    const int bn  = blockIdx.x;
    const int b   = bn >> 7;     /* N = 128 */
    const int n   = bn & 127;

    if (tid == 0) {
        sxmin = 1 << 30; symin = 1 << 30;
        sxmax = -(1 << 30); symax = -(1 << 30);
    }
    __syncthreads();

    if (tid < GP) {
        const float* roi = rois + (size_t)(b * NN + n) * 7;
        float fstride = (float)stridep[0];
        float vx = voxel[0] * fstride;
        float vy = voxel[1] * fstride;
        float cx = roi[0], cy = roi[1];
        float dx = roi[3], dy = roi[4];
        float ang = roi[6];
        /* MIN_X = 0, MIN_Y = -40 */
        float x1 = (cx - dx * 0.5f - 0.0f) / vx;
        float x2 = (cx + dx * 0.5f - 0.0f) / vx;
        float y1 = (cy - dy * 0.5f + 40.0f) / vy;
        float y2 = (cy + dy * 0.5f + 40.0f) / vy;
        float cosa = cosf(ang), sina = sinf(ang);
        float scale1 = (y2 - y1) / fmaxf(x2 - x1, 0.01f);
        float scale2 = (x2 - x1) / fmaxf(y2 - y1, 0.01f);
        float t00 = (x2 - x1) / (float)(WW - 1) * cosa;
        float t01 = (x2 - x1) / (float)(WW - 1) * (-sina) * scale1;
        float t02 = (x1 + x2 - (float)WW + 1.0f) / (float)(WW - 1);
        float t10 = (y2 - y1) / (float)(HH - 1) * sina * scale2;
        float t11 = (y2 - y1) / (float)(HH - 1) * cosa;
        float t12 = (y1 + y2 - (float)HH + 1.0f) / (float)(HH - 1);
        int r = tid / GG, q = tid - r * GG;
        float xx = (2.0f * (float)q + 1.0f) / (float)GG - 1.0f;
        float yy = (2.0f * (float)r + 1.0f) / (float)GG - 1.0f;
        float gx = t00 * xx + t01 * yy + t02;
        float gy = t10 * xx + t11 * yy + t12;
        float ix = ((gx + 1.0f) * (float)WW - 1.0f) * 0.5f;
        float iy = ((gy + 1.0f) * (float)HH - 1.0f) * 0.5f;
        six[tid] = ix; siy[tid] = iy;
        /* clamped corner indices for bbox reduction */
        float x0f = floorf(ix), y0f = floorf(iy);
        int x0c = (int)fminf(fmaxf(x0f,        0.0f), (float)(WW - 1));
        int x1c = (int)fminf(fmaxf(x0f + 1.0f, 0.0f), (float)(WW - 1));
        int y0c = (int)fminf(fmaxf(y0f,        0.0f), (float)(HH - 1));
        int y1c = (int)fminf(fmaxf(y0f + 1.0f, 0.0f), (float)(HH - 1));
        atomicMin(&sxmin, x0c); atomicMax(&sxmax, x1c);
        atomicMin(&symin, y0c); atomicMax(&symax, y1c);
    }
    __syncthreads();
    if (tid == 0) {
        int w = sxmax - sxmin + 1;
        int h = symax - symin + 1;
        bxmin = sxmin; bymin = symin; bw = w; bh = h;
        sfits = (w * h <= TS) ? 1 : 0;
    }
    __syncthreads();
    const int fits = sfits;
    const int xmin = bxmin, ymin = bymin, wbox = bw, hbox = bh;

    if (tid < GP) {
        float ix = six[tid], iy = siy[tid];
        float x0f = floorf(ix), y0f = floorf(iy);
        float wx1 = ix - x0f, wx0 = 1.0f - wx1;
        float wy1 = iy - y0f, wy0 = 1.0f - wy1;
        float x1f = x0f + 1.0f, y1f = y0f + 1.0f;
        float vx0 = (x0f >= 0.0f && x0f <= (float)(WW - 1)) ? 1.0f : 0.0f;
        float vx1 = (x1f >= 0.0f && x1f <= (float)(WW - 1)) ? 1.0f : 0.0f;
        float vy0 = (y0f >= 0.0f && y0f <= (float)(HH - 1)) ? 1.0f : 0.0f;
        float vy1 = (y1f >= 0.0f && y1f <= (float)(HH - 1)) ? 1.0f : 0.0f;
        int x0c = (int)fminf(fmaxf(x0f, 0.0f), (float)(WW - 1));
        int x1c = (int)fminf(fmaxf(x1f, 0.0f), (float)(WW - 1));
        int y0c = (int)fminf(fmaxf(y0f, 0.0f), (float)(HH - 1));
        int y1c = (int)fminf(fmaxf(y1f, 0.0f), (float)(HH - 1));
        int rowstride = fits ? wbox : WW;
        int xo = fits ? xmin : 0;
        int yo = fits ? ymin : 0;
        ploc[tid] = (y0c - yo) * rowstride + (x0c - xo);
        psx[tid]  = x1c - x0c;                 /* 0 or 1 */
        psy[tid]  = (y1c - y0c) * rowstride;   /* 0 or rowstride */
        pw0[tid] = wy0 * wx0 * vy0 * vx0;
        pw1[tid] = wy0 * wx1 * vy0 * vx1;
        pw2[tid] = wy1 * wx0 * vy1 * vx0;
        pw3[tid] = wy1 * wx1 * vy1 * vx1;
    }
    /* first chunk-loop barrier covers the param phase */

    const int wid  = tid >> 5, lane = tid & 31;
    const int cl   = tid & (CH - 1);
    const int pg   = tid / CH;               /* 16 point-groups */
    const size_t HW = (size_t)HH * WW;
    const float* fb = feat + (size_t)b * CC * HW;
    float* ob = out + (size_t)bn * CC * GP;

    for (int c0 = 0; c0 < CC; c0 += CH) {
        __syncthreads();  /* tile + sout safe to overwrite */
        if (fits) {
            const float* src0 = fb + (size_t)c0 * HW + (size_t)ymin * WW + xmin;
            #pragma unroll 1
            for (int cc = 0; cc < CH; ++cc) {
                const float* src = src0 + (size_t)cc * HW;
                float* dst = tile + cc * TS;
                for (int r = wid; r < hbox; r += 8) {
                    const float* srow = src + (size_t)r * WW;
                    float* drow = dst + r * wbox;
                    for (int col = lane; col < wbox; col += 32)
                        drow[col] = __ldg(srow + col);
                }
            }
            __syncthreads();
            const float* t = tile + cl * TS;
            for (int p = pg; p < GP; p += (THREADS / CH)) {
                int loc = ploc[p], sx = psx[p], sy = psy[p];
                float v = pw0[p] * t[loc]
                        + pw1[p] * t[loc + sx]
                        + pw2[p] * t[loc + sy]
                        + pw3[p] * t[loc + sy + sx];
                sout[cl * GP + p] = v;
            }
        } else {
            /* fallback: direct gmem gather (unreachable with these input ranges) */
            const float* t = fb + (size_t)(c0 + cl) * HW;
            for (int p = pg; p < GP; p += (THREADS / CH)) {
                int loc = ploc[p], sx = psx[p], sy = psy[p];
                float v = pw0[p] * __ldg(t + loc)
                        + pw1[p] * __ldg(t + loc + sx)
                        + pw2[p] * __ldg(t + loc + sy)
                        + pw3[p] * __ldg(t + loc + sy + sx);
                sout[cl * GP + p] = v;
            }
        }
        __syncthreads();
        float* od = ob + (size_t)c0 * GP;
        for (int e = tid; e < CH * GP; e += THREADS)
            od[e] = sout[e];
    }
}

extern "C" void kernel_launch(void* const* d_in, const int* in_sizes, int n_in,
                              void* d_out, int out_size)
{
    const float* feat   = (const float*)d_in[0];
    const float* rois   = (const float*)d_in[1];
    const float* voxel  = (const float*)d_in[2];
    const int*   stride = (const int*)d_in[3];
    float* out = (float*)d_out;
    (void)in_sizes; (void)n_in; (void)out_size;
    rotpool_kernel<<<BB * NN, THREADS>>>(feat, rois, voxel, stride, out);
}

// round 2
// speedup vs baseline: 5.6738x; 5.6738x over previous
#include <cuda_runtime.h>
#include <cuda_bf16.h>
#include <math.h>

#define BB 4
#define CC 256
#define HH 200
#define WW 176
#define NN 128
#define GG 7
#define GP 49
#define NW 8          /* warps per block */
#define THREADS 256
#define TROWS 20      /* tile row capacity */
#define TSMAX 28      /* max smem row stride (wb+4), floats */
#define TCAP (TROWS * TSMAX)   /* 560 floats per warp tile */

__global__ __launch_bounds__(THREADS) void rotpool_kernel(
    const float* __restrict__ feat, const float* __restrict__ rois,
    const float* __restrict__ voxel, const int* __restrict__ stridep,
    float* __restrict__ out)
{
    __shared__ __align__(16) float tile[NW][TCAP];
    __shared__ __align__(16) int4   poff[GP];
    __shared__ __align__(16) float4 pwt[GP];
    __shared__ int sxmin, sxmax, symin, symax;
    __shared__ int s_x0, s_y0, s_wb4, s_hb, s_ts, s_fits;
    __shared__ unsigned s_mag;

    const int tid  = threadIdx.x;
    const int lane = tid & 31;
    const int w    = tid >> 5;
    const int bn   = blockIdx.x;
    const int b    = bn >> 7;          /* N = 128 */

    if (tid == 0) {
        sxmin = 1 << 30; symin = 1 << 30;
        sxmax = -(1 << 30); symax = -(1 << 30);
    }
    __syncthreads();

    float ix = 0.f, iy = 0.f;
    if (tid < GP) {
        const float* roi = rois + (size_t)bn * 7;
        float fstride = (float)stridep[0];
        float vx = voxel[0] * fstride;
        float vy = voxel[1] * fstride;
        float cx = roi[0], cy = roi[1];
        float dx = roi[3], dy = roi[4];
        float ang = roi[6];
        /* MIN_X = 0, MIN_Y = -40 */
        float x1 = (cx - dx * 0.5f) / vx;
        float x2 = (cx + dx * 0.5f) / vx;
        float y1 = (cy - dy * 0.5f + 40.0f) / vy;
        float y2 = (cy + dy * 0.5f + 40.0f) / vy;
        float cosa = cosf(ang), sina = sinf(ang);
        float scale1 = (y2 - y1) / fmaxf(x2 - x1, 0.01f);
        float scale2 = (x2 - x1) / fmaxf(y2 - y1, 0.01f);
        float t00 = (x2 - x1) / (float)(WW - 1) * cosa;
        float t01 = (x2 - x1) / (float)(WW - 1) * (-sina) * scale1;
        float t02 = (x1 + x2 - (float)WW + 1.0f) / (float)(WW - 1);
        float t10 = (y2 - y1) / (float)(HH - 1) * sina * scale2;
        float t11 = (y2 - y1) / (float)(HH - 1) * cosa;
        float t12 = (y1 + y2 - (float)HH + 1.0f) / (float)(HH - 1);
        int r = tid / GG, q = tid - r * GG;
        float xx = (2.0f * (float)q + 1.0f) / (float)GG - 1.0f;
        float yy = (2.0f * (float)r + 1.0f) / (float)GG - 1.0f;
        float gx = t00 * xx + t01 * yy + t02;
        float gy = t10 * xx + t11 * yy + t12;
        ix = ((gx + 1.0f) * (float)WW - 1.0f) * 0.5f;
        iy = ((gy + 1.0f) * (float)HH - 1.0f) * 0.5f;
        float x0f = floorf(ix), y0f = floorf(iy);
        int x0c = (int)fminf(fmaxf(x0f,        0.0f), (float)(WW - 1));
        int x1c = (int)fminf(fmaxf(x0f + 1.0f, 0.0f), (float)(WW - 1));
        int y0c = (int)fminf(fmaxf(y0f,        0.0f), (float)(HH - 1));
        int y1c = (int)fminf(fmaxf(y0f + 1.0f, 0.0f), (float)(HH - 1));
        atomicMin(&sxmin, x0c); atomicMax(&sxmax, x1c);
        atomicMin(&symin, y0c); atomicMax(&symax, y1c);
    }
    __syncthreads();

    if (tid == 0) {
        int x0 = sxmin & ~7;                       /* 8-float (32B) aligned */
        int wb = ((sxmax - x0 + 1) + 7) & ~7;      /* multiple of 8, <= 176-x0 */
        int hb = symax - symin + 1;
        int fits = (hb <= TROWS) && ((wb + 4) <= TSMAX);
        s_x0 = x0; s_y0 = symin;
        s_wb4 = wb >> 2;
        s_hb = hb;
        s_ts = wb + 4;                             /* padded smem row stride */
        s_fits = fits;
        s_mag = (unsigned)(0xFFFFFFFFu / (unsigned)(wb >> 2)) + 1u;
    }
    __syncthreads();
    const int fits = s_fits;
    const int x0 = s_x0, y0v = s_y0, wb4 = s_wb4, hb = s_hb, ts = s_ts;
    const unsigned mag = s_mag;

    if (tid < GP) {
        float x0f = floorf(ix), y0f = floorf(iy);
        float wx1 = ix - x0f, wx0 = 1.0f - wx1;
        float wy1 = iy - y0f, wy0 = 1.0f - wy1;
        float x1f = x0f + 1.0f, y1f = y0f + 1.0f;
        float vx0 = (x0f >= 0.0f && x0f <= (float)(WW - 1)) ? 1.0f : 0.0f;
        float vx1 = (x1f >= 0.0f && x1f <= (float)(WW - 1)) ? 1.0f : 0.0f;
        float vy0 = (y0f >= 0.0f && y0f <= (float)(HH - 1)) ? 1.0f : 0.0f;
        float vy1 = (y1f >= 0.0f && y1f <= (float)(HH - 1)) ? 1.0f : 0.0f;
        int x0c = (int)fminf(fmaxf(x0f, 0.0f), (float)(WW - 1));
        int x1c = (int)fminf(fmaxf(x1f, 0.0f), (float)(WW - 1));
        int y0c = (int)fminf(fmaxf(y0f, 0.0f), (float)(HH - 1));
        int y1c = (int)fminf(fmaxf(y1f, 0.0f), (float)(HH - 1));
        int rs = fits ? ts : WW;
        int xo = fits ? x0 : 0;
        int yo = fits ? y0v : 0;
        int l0 = (y0c - yo) * rs + (x0c - xo);
        int sx = x1c - x0c;
        int sy = (y1c - y0c) * rs;
        poff[tid] = make_int4(l0, l0 + sx, l0 + sy, l0 + sy + sx);
        pwt[tid]  = make_float4(wy0 * wx0 * vy0 * vx0,
                                wy0 * wx1 * vy0 * vx1,
                                wy1 * wx0 * vy1 * vx0,
                                wy1 * wx1 * vy1 * vx1);
    }
    __syncthreads();

    const size_t HWs = (size_t)HH * WW;
    const float* fb = feat + (size_t)b * CC * HWs;
    float* ob = out + (size_t)bn * CC * GP;
    float* mytile = tile[w];

    if (fits) {
        const int total4 = hb * wb4;
        #pragma unroll 1
        for (int c = w; c < CC; c += NW) {
            const float4* src = (const float4*)(fb + (size_t)c * HWs
                                                + (size_t)y0v * WW + x0);
            #pragma unroll 4
            for (int e = lane; e < total4; e += 32) {
                int r   = (int)__umulhi((unsigned)e, mag);
                int col = e - r * wb4;
                float4 v = __ldg(src + r * (WW / 4) + col);
                *(float4*)(mytile + r * ts + col * 4) = v;
            }
            __syncwarp();
            #pragma unroll
            for (int p0 = 0; p0 < 64; p0 += 32) {
                int p = p0 + lane;
                if (p < GP) {
                    int4   o  = poff[p];
                    float4 wt = pwt[p];
                    float v = wt.x * mytile[o.x] + wt.y * mytile[o.y]
                            + wt.z * mytile[o.z] + wt.w * mytile[o.w];
                    ob[(size_t)c * GP + p] = v;
                }
            }
            __syncwarp();
        }
    } else {
        /* unreachable with these input ranges; direct gmem gather */
        #pragma unroll 1
        for (int c = w; c < CC; c += NW) {
            const float* plane = fb + (size_t)c * HWs;
            #pragma unroll
            for (int p0 = 0; p0 < 64; p0 += 32) {
                int p = p0 + lane;
                if (p < GP) {
                    int4   o  = poff[p];
                    float4 wt = pwt[p];
                    float v = wt.x * __ldg(plane + o.x) + wt.y * __ldg(plane + o.y)
                            + wt.z * __ldg(plane + o.z) + wt.w * __ldg(plane + o.w);
                    ob[(size_t)c * GP + p] = v;
                }
            }
        }
    }
}

extern "C" void kernel_launch(void* const* d_in, const int* in_sizes, int n_in,
                              void* d_out, int out_size)
{
    const float* feat   = (const float*)d_in[0];
    const float* rois   = (const float*)d_in[1];
    const float* voxel  = (const float*)d_in[2];
    const int*   stride = (const int*)d_in[3];
    float* out = (float*)d_out;
    (void)in_sizes; (void)n_in; (void)out_size;
    rotpool_kernel<<<BB * NN, THREADS>>>(feat, rois, voxel, stride, out);
}

// round 3
// speedup vs baseline: 7.9766x; 1.4059x over previous
#include <cuda_runtime.h>
#include <cuda_bf16.h>
#include <math.h>

#define BB 4
#define CC 256
#define NN 128
#define HH 200
#define WW 176
#define GG 7
#define GP 49
#define NW 8            /* warps per block */
#define THREADS 256
#define CSPLIT 2        /* blocks per ROI (channel split) */
#define CPB (CC / CSPLIT)   /* 128 channels per block */
#define TROWS 20        /* tile row capacity */
#define TSMAX 28        /* max smem row stride (wb+4), floats */
#define TCAP (TROWS * TSMAX)

__global__ __launch_bounds__(THREADS) void rotpool_kernel(
    const float* __restrict__ feat, const float* __restrict__ rois,
    const float* __restrict__ voxel, const int* __restrict__ stridep,
    float* __restrict__ out)
{
    __shared__ __align__(16) float tile[NW][TCAP];
    __shared__ __align__(16) int4   poff[64];
    __shared__ __align__(16) float4 pwt[64];
    __shared__ int sxmin, sxmax, symin, symax;
    __shared__ int s_x0, s_y0, s_wb4, s_hb, s_ts, s_fits;

    const int tid  = threadIdx.x;
    const int lane = tid & 31;
    const int w    = tid >> 5;
    const int blk  = blockIdx.x;
    const int bn   = blk >> 1;             /* ROI index (0..511) */
    const int half = blk & 1;              /* channel half */
    const int b    = bn >> 7;              /* batch */

    if (tid == 0) {
        sxmin = 1 << 30; symin = 1 << 30;
        sxmax = -(1 << 30); symax = -(1 << 30);
    }
    if (tid >= GP && tid < 64) {           /* pad so reg loads are safe */
        poff[tid] = make_int4(0, 0, 0, 0);
        pwt[tid]  = make_float4(0.f, 0.f, 0.f, 0.f);
    }
    __syncthreads();

    float ix = 0.f, iy = 0.f;
    if (tid < GP) {
        const float* roi = rois + (size_t)bn * 7;
        float fstride = (float)stridep[0];
        float vx = voxel[0] * fstride;
        float vy = voxel[1] * fstride;
        float cx = roi[0], cy = roi[1];
        float dx = roi[3], dy = roi[4];
        float ang = roi[6];
        float x1 = (cx - dx * 0.5f) / vx;
        float x2 = (cx + dx * 0.5f) / vx;
        float y1 = (cy - dy * 0.5f + 40.0f) / vy;
        float y2 = (cy + dy * 0.5f + 40.0f) / vy;
        float cosa = cosf(ang), sina = sinf(ang);
        float scale1 = (y2 - y1) / fmaxf(x2 - x1, 0.01f);
        float scale2 = (x2 - x1) / fmaxf(y2 - y1, 0.01f);
        float t00 = (x2 - x1) / (float)(WW - 1) * cosa;
        float t01 = (x2 - x1) / (float)(WW - 1) * (-sina) * scale1;
        float t02 = (x1 + x2 - (float)WW + 1.0f) / (float)(WW - 1);
        float t10 = (y2 - y1) / (float)(HH - 1) * sina * scale2;
        float t11 = (y2 - y1) / (float)(HH - 1) * cosa;
        float t12 = (y1 + y2 - (float)HH + 1.0f) / (float)(HH - 1);
        int r = tid / GG, q = tid - r * GG;
        float xx = (2.0f * (float)q + 1.0f) / (float)GG - 1.0f;
        float yy = (2.0f * (float)r + 1.0f) / (float)GG - 1.0f;
        float gx = t00 * xx + t01 * yy + t02;
        float gy = t10 * xx + t11 * yy + t12;
        ix = ((gx + 1.0f) * (float)WW - 1.0f) * 0.5f;
        iy = ((gy + 1.0f) * (float)HH - 1.0f) * 0.5f;
        float x0f = floorf(ix), y0f = floorf(iy);
        int x0c = (int)fminf(fmaxf(x0f,        0.0f), (float)(WW - 1));
        int x1c = (int)fminf(fmaxf(x0f + 1.0f, 0.0f), (float)(WW - 1));
        int y0c = (int)fminf(fmaxf(y0f,        0.0f), (float)(HH - 1));
        int y1c = (int)fminf(fmaxf(y0f + 1.0f, 0.0f), (float)(HH - 1));
        atomicMin(&sxmin, x0c); atomicMax(&sxmax, x1c);
        atomicMin(&symin, y0c); atomicMax(&symax, y1c);
    }
    __syncthreads();

    if (tid == 0) {
        int x0 = sxmin & ~7;
        int wb = ((sxmax - x0 + 1) + 7) & ~7;
        int hb = symax - symin + 1;
        int fits = (hb <= TROWS) && ((wb + 4) <= TSMAX);
        s_x0 = x0; s_y0 = symin;
        s_wb4 = wb >> 2;
        s_hb = hb;
        s_ts = wb + 4;
        s_fits = fits;
    }
    __syncthreads();
    const int fits = s_fits;
    const int x0 = s_x0, y0v = s_y0, wb4 = s_wb4, hb = s_hb, ts = s_ts;

    if (tid < GP) {
        float x0f = floorf(ix), y0f = floorf(iy);
        float wx1 = ix - x0f, wx0 = 1.0f - wx1;
        float wy1 = iy - y0f, wy0 = 1.0f - wy1;
        float x1f = x0f + 1.0f, y1f = y0f + 1.0f;
        float vx0 = (x0f >= 0.0f && x0f <= (float)(WW - 1)) ? 1.0f : 0.0f;
        float vx1 = (x1f >= 0.0f && x1f <= (float)(WW - 1)) ? 1.0f : 0.0f;
        float vy0 = (y0f >= 0.0f && y0f <= (float)(HH - 1)) ? 1.0f : 0.0f;
        float vy1 = (y1f >= 0.0f && y1f <= (float)(HH - 1)) ? 1.0f : 0.0f;
        int x0c = (int)fminf(fmaxf(x0f, 0.0f), (float)(WW - 1));
        int x1c = (int)fminf(fmaxf(x1f, 0.0f), (float)(WW - 1));
        int y0c = (int)fminf(fmaxf(y0f, 0.0f), (float)(HH - 1));
        int y1c = (int)fminf(fmaxf(y1f, 0.0f), (float)(HH - 1));
        int rs = fits ? ts : WW;
        int xo = fits ? x0 : 0;
        int yo = fits ? y0v : 0;
        int l0 = (y0c - yo) * rs + (x0c - xo);
        int sx = x1c - x0c;
        int sy = (y1c - y0c) * rs;
        poff[tid] = make_int4(l0, l0 + sx, l0 + sy, l0 + sy + sx);
        pwt[tid]  = make_float4(wy0 * wx0 * vy0 * vx0,
                                wy0 * wx1 * vy0 * vx1,
                                wy1 * wx0 * vy1 * vx0,
                                wy1 * wx1 * vy1 * vx1);
    }
    __syncthreads();

    /* hoist channel-invariant params into registers */
    const int4   o0 = poff[lane];
    const float4 w0 = pwt[lane];
    const int4   o1 = poff[lane + 32];
    const float4 w1 = pwt[lane + 32];
    const bool   p1ok = (lane + 32) < GP;

    const size_t HWs = (size_t)HH * WW;
    const float* fb = feat + (size_t)b * CC * HWs;
    float* ob = out + (size_t)bn * CC * GP;
    float* mytile = tile[w];
    const int cbeg = half * CPB + w;
    const int cend = half * CPB + CPB;

    if (fits) {
        const int total4 = hb * wb4;
        /* per-lane fixed addresses for up to 4 float4 elements */
        int goff[4], soff[4];
        bool act[4];
        #pragma unroll
        for (int i = 0; i < 4; ++i) {
            int e = lane + 32 * i;
            act[i] = e < total4;
            int r = e / wb4;             /* once, cheap */
            int col = e - r * wb4;
            goff[i] = r * (WW / 4) + col;
            soff[i] = r * ts + col * 4;
        }
        const float4* srcbase = (const float4*)(fb + (size_t)y0v * WW + x0);
        const int planestep4 = (int)(HWs >> 2);

        /* preload first channel */
        float4 rv[4];
        {
            const float4* src = srcbase + (size_t)cbeg * planestep4;
            #pragma unroll
            for (int i = 0; i < 4; ++i)
                if (act[i]) rv[i] = __ldg(src + goff[i]);
        }

        #pragma unroll 1
        for (int c = cbeg; c < cend; c += NW) {
            /* commit prefetched tile */
            #pragma unroll
            for (int i = 0; i < 4; ++i)
                if (act[i]) *(float4*)(mytile + soff[i]) = rv[i];
            __syncwarp();

            /* prefetch next channel while computing this one */
            int cn = c + NW;
            if (cn < cend) {
                const float4* src = srcbase + (size_t)cn * planestep4;
                #pragma unroll
                for (int i = 0; i < 4; ++i)
                    if (act[i]) rv[i] = __ldg(src + goff[i]);
            }

            float v0 = w0.x * mytile[o0.x] + w0.y * mytile[o0.y]
                     + w0.z * mytile[o0.z] + w0.w * mytile[o0.w];
            float* od = ob + (size_t)c * GP;
            od[lane] = v0;
            if (p1ok) {
                float v1 = w1.x * mytile[o1.x] + w1.y * mytile[o1.y]
                         + w1.z * mytile[o1.z] + w1.w * mytile[o1.w];
                od[lane + 32] = v1;
            }
            __syncwarp();
        }
    } else {
        /* unreachable with these input ranges; direct gmem gather */
        #pragma unroll 1
        for (int c = cbeg; c < cend; c += NW) {
            const float* plane = fb + (size_t)c * HWs;
            float v0 = w0.x * __ldg(plane + o0.x) + w0.y * __ldg(plane + o0.y)
                     + w0.z * __ldg(plane + o0.z) + w0.w * __ldg(plane + o0.w);
            float* od = ob + (size_t)c * GP;
            od[lane] = v0;
            if (p1ok) {
                float v1 = w1.x * __ldg(plane + o1.x) + w1.y * __ldg(plane + o1.y)
                         + w1.z * __ldg(plane + o1.z) + w1.w * __ldg(plane + o1.w);
                od[lane + 32] = v1;
            }
        }
    }
}

extern "C" void kernel_launch(void* const* d_in, const int* in_sizes, int n_in,
                              void* d_out, int out_size)
{
    const float* feat   = (const float*)d_in[0];
    const float* rois   = (const float*)d_in[1];
    const float* voxel  = (const float*)d_in[2];
    const int*   stride = (const int*)d_in[3];
    float* out = (float*)d_out;
    (void)in_sizes; (void)n_in; (void)out_size;
    rotpool_kernel<<<BB * NN * CSPLIT, THREADS>>>(feat, rois, voxel, stride, out);
}

// round 5
// speedup vs baseline: 9.9395x; 1.2461x over previous
#include <cuda_runtime.h>
#include <cuda_bf16.h>
#include <math.h>

#define BB 4
#define CC 256
#define NN 128
#define HH 200
#define WW 176
#define GG 7
#define GP 49
#define NW 4            /* warps per block */
#define THREADS 128
#define CSPLIT 8        /* blocks per ROI (channel split) */
#define CPB (CC / CSPLIT)   /* 32 channels per block */
#define TROWS 20        /* tile row capacity */
#define TSMAX 28        /* max smem row stride (wb+4), floats */
#define TCAP (TROWS * TSMAX)

__device__ __forceinline__ void cpa16(unsigned s, const void* g) {
    asm volatile("cp.async.cg.shared.global [%0], [%1], 16;" :: "r"(s), "l"(g));
}
__device__ __forceinline__ void cpa_commit() {
    asm volatile("cp.async.commit_group;");
}
__device__ __forceinline__ void cpa_wait1() {
    asm volatile("cp.async.wait_group 1;");
}

__global__ __launch_bounds__(THREADS, 10) void rotpool_kernel(
    const float* __restrict__ feat, const float* __restrict__ rois,
    const float* __restrict__ voxel, const int* __restrict__ stridep,
    float* __restrict__ out)
{
    __shared__ __align__(16) float tile[2][NW][TCAP];
    __shared__ __align__(16) int4   poff[64];
    __shared__ __align__(16) float4 pwt[64];
    __shared__ int sxmin, sxmax, symin, symax;
    __shared__ int s_x0, s_y0, s_wb4, s_hb, s_ts, s_fits;

    const int tid  = threadIdx.x;
    const int lane = tid & 31;
    const int w    = tid >> 5;
    const int blk  = blockIdx.x;
    const int bn   = blk >> 3;             /* ROI index (0..511) */
    const int part = blk & 7;              /* channel slice    */
    const int b    = bn >> 7;              /* batch */

    if (tid == 0) {
        sxmin = 1 << 30; symin = 1 << 30;
        sxmax = -(1 << 30); symax = -(1 << 30);
    }
    if (tid >= GP && tid < 64) {
        poff[tid] = make_int4(0, 0, 0, 0);
        pwt[tid]  = make_float4(0.f, 0.f, 0.f, 0.f);
    }
    __syncthreads();

    float ix = 0.f, iy = 0.f;
    if (tid < GP) {
        const float* roi = rois + (size_t)bn * 7;
        float fstride = (float)stridep[0];
        float vx = voxel[0] * fstride;
        float vy = voxel[1] * fstride;
        float cx = roi[0], cy = roi[1];
        float dx = roi[3], dy = roi[4];
        float ang = roi[6];
        float x1 = (cx - dx * 0.5f) / vx;
        float x2 = (cx + dx * 0.5f) / vx;
        float y1 = (cy - dy * 0.5f + 40.0f) / vy;
        float y2 = (cy + dy * 0.5f + 40.0f) / vy;
        float cosa = cosf(ang), sina = sinf(ang);
        float scale1 = (y2 - y1) / fmaxf(x2 - x1, 0.01f);
        float scale2 = (x2 - x1) / fmaxf(y2 - y1, 0.01f);
        float t00 = (x2 - x1) / (float)(WW - 1) * cosa;
        float t01 = (x2 - x1) / (float)(WW - 1) * (-sina) * scale1;
        float t02 = (x1 + x2 - (float)WW + 1.0f) / (float)(WW - 1);
        float t10 = (y2 - y1) / (float)(HH - 1) * sina * scale2;
        float t11 = (y2 - y1) / (float)(HH - 1) * cosa;
        float t12 = (y1 + y2 - (float)HH + 1.0f) / (float)(HH - 1);
        int r = tid / GG, q = tid - r * GG;
        float xx = (2.0f * (float)q + 1.0f) / (float)GG - 1.0f;
        float yy = (2.0f * (float)r + 1.0f) / (float)GG - 1.0f;
        float gx = t00 * xx + t01 * yy + t02;
        float gy = t10 * xx + t11 * yy + t12;
        ix = ((gx + 1.0f) * (float)WW - 1.0f) * 0.5f;
        iy = ((gy + 1.0f) * (float)HH - 1.0f) * 0.5f;
        float x0f = floorf(ix), y0f = floorf(iy);
        int x0c = (int)fminf(fmaxf(x0f,        0.0f), (float)(WW - 1));
        int x1c = (int)fminf(fmaxf(x0f + 1.0f, 0.0f), (float)(WW - 1));
        int y0c = (int)fminf(fmaxf(y0f,        0.0f), (float)(HH - 1));
        int y1c = (int)fminf(fmaxf(y0f + 1.0f, 0.0f), (float)(HH - 1));
        atomicMin(&sxmin, x0c); atomicMax(&sxmax, x1c);
        atomicMin(&symin, y0c); atomicMax(&symax, y1c);
    }
    __syncthreads();

    if (tid == 0) {
        int x0 = sxmin & ~7;
        int wb = ((sxmax - x0 + 1) + 7) & ~7;
        int hb = symax - symin + 1;
        int fits = (hb <= TROWS) && ((wb + 4) <= TSMAX);
        s_x0 = x0; s_y0 = symin;
        s_wb4 = wb >> 2;
        s_hb = hb;
        s_ts = wb + 4;
        s_fits = fits;
    }
    __syncthreads();
    const int fits = s_fits;
    const int x0 = s_x0, y0v = s_y0, wb4 = s_wb4, hb = s_hb, ts = s_ts;

    if (tid < GP) {
        float x0f = floorf(ix), y0f = floorf(iy);
        float wx1 = ix - x0f, wx0 = 1.0f - wx1;
        float wy1 = iy - y0f, wy0 = 1.0f - wy1;
        float x1f = x0f + 1.0f, y1f = y0f + 1.0f;
        float vx0 = (x0f >= 0.0f && x0f <= (float)(WW - 1)) ? 1.0f : 0.0f;
        float vx1 = (x1f >= 0.0f && x1f <= (float)(WW - 1)) ? 1.0f : 0.0f;
        float vy0 = (y0f >= 0.0f && y0f <= (float)(HH - 1)) ? 1.0f : 0.0f;
        float vy1 = (y1f >= 0.0f && y1f <= (float)(HH - 1)) ? 1.0f : 0.0f;
        int x0c = (int)fminf(fmaxf(x0f, 0.0f), (float)(WW - 1));
        int x1c = (int)fminf(fmaxf(x1f, 0.0f), (float)(WW - 1));
        int y0c = (int)fminf(fmaxf(y0f, 0.0f), (float)(HH - 1));
        int y1c = (int)fminf(fmaxf(y1f, 0.0f), (float)(HH - 1));
        int rs = fits ? ts : WW;
        int xo = fits ? x0 : 0;
        int yo = fits ? y0v : 0;
        int l0 = (y0c - yo) * rs + (x0c - xo);
        int sx = x1c - x0c;
        int sy = (y1c - y0c) * rs;
        poff[tid] = make_int4(l0, l0 + sx, l0 + sy, l0 + sy + sx);
        pwt[tid]  = make_float4(wy0 * wx0 * vy0 * vx0,
                                wy0 * wx1 * vy0 * vx1,
                                wy1 * wx0 * vy1 * vx0,
                                wy1 * wx1 * vy1 * vx1);
    }
    __syncthreads();

    /* channel-invariant gather params in registers */
    const int4   o0 = poff[lane];
    const float4 w0 = pwt[lane];
    const int4   o1 = poff[lane + 32];
    const float4 w1 = pwt[lane + 32];
    const bool   p1ok = (lane + 32) < GP;

    const size_t HWs = (size_t)HH * WW;
    const float* fb = feat + (size_t)b * CC * HWs;
    float* ob = out + (size_t)bn * CC * GP;
    const int cbeg = part * CPB + w;
    const int cend = part * CPB + CPB;

    if (fits) {
        const int total4 = hb * wb4;
        /* per-lane fixed addresses (<=4 float4 elements) */
        int goff[4]; unsigned sboff[4]; bool act[4];
        #pragma unroll
        for (int i = 0; i < 4; ++i) {
            int e = lane + 32 * i;
            act[i] = e < total4;
            int r = e / wb4;
            int col = e - r * wb4;
            goff[i]  = r * (WW / 4) + col;
            sboff[i] = (unsigned)((r * ts + col * 4) * 4);
        }
        float* t0 = tile[0][w];
        float* t1 = tile[1][w];
        const unsigned sb0 = (unsigned)__cvta_generic_to_shared(t0);
        const unsigned sb1 = (unsigned)__cvta_generic_to_shared(t1);
        const float4* srcbase = (const float4*)(fb + (size_t)y0v * WW + x0);
        const int planestep4 = (int)(HWs >> 2);

        /* prologue: stage channel cbeg into buffer 0 */
        {
            const float4* src = srcbase + (size_t)cbeg * planestep4;
            #pragma unroll
            for (int i = 0; i < 4; ++i)
                if (act[i]) cpa16(sb0 + sboff[i], src + goff[i]);
            cpa_commit();
        }

        int p = 0;
        #pragma unroll 1
        for (int c = cbeg; c < cend; c += NW) {
            int cn = c + NW;
            if (cn < cend) {
                const unsigned sbn = p ? sb0 : sb1;
                const float4* src = srcbase + (size_t)cn * planestep4;
                #pragma unroll
                for (int i = 0; i < 4; ++i)
                    if (act[i]) cpa16(sbn + sboff[i], src + goff[i]);
            }
            cpa_commit();
            cpa_wait1();
            __syncwarp();

            const float* tc = p ? t1 : t0;
            float v0 = w0.x * tc[o0.x] + w0.y * tc[o0.y]
                     + w0.z * tc[o0.z] + w0.w * tc[o0.w];
            float* od = ob + (size_t)c * GP;
            od[lane] = v0;
            if (p1ok) {
                float v1 = w1.x * tc[o1.x] + w1.y * tc[o1.y]
                         + w1.z * tc[o1.z] + w1.w * tc[o1.w];
                od[lane + 32] = v1;
            }
            __syncwarp();
            p ^= 1;
        }
    } else {
        /* unreachable with these input ranges; direct gmem gather */
        #pragma unroll 1
        for (int c = cbeg; c < cend; c += NW) {
            const float* plane = fb + (size_t)c * HWs;
            float v0 = w0.x * __ldg(plane + o0.x) + w0.y * __ldg(plane + o0.y)
                     + w0.z * __ldg(plane + o0.z) + w0.w * __ldg(plane + o0.w);
            float* od = ob + (size_t)c * GP;
            od[lane] = v0;
            if (p1ok) {
                float v1 = w1.x * __ldg(plane + o1.x) + w1.y * __ldg(plane + o1.y)
                         + w1.z * __ldg(plane + o1.z) + w1.w * __ldg(plane + o1.w);
                od[lane + 32] = v1;
            }
        }
    }
}

extern "C" void kernel_launch(void* const* d_in, const int* in_sizes, int n_in,
                              void* d_out, int out_size)
{
    const float* feat   = (const float*)d_in[0];
    const float* rois   = (const float*)d_in[1];
    const float* voxel  = (const float*)d_in[2];
    const int*   stride = (const int*)d_in[3];
    float* out = (float*)d_out;
    (void)in_sizes; (void)n_in; (void)out_size;
    rotpool_kernel<<<BB * NN * CSPLIT, THREADS>>>(feat, rois, voxel, stride, out);
}